// round 11
// baseline (speedup 1.0000x reference)
#include <cuda_runtime.h>
#include <cuda_bf16.h>
#include <cstdint>

// Problem constants
#define L_SEQ  16384
#define H_DIM  1024
#define P_DIM  256
#define PP_DIM 512          // 2*P : [re | im] planes
#define NCHUNK 256
#define S_CHUNK 64          // L = NCHUNK * S_CHUNK

// ----------------------------------------------------------------------------
// Device scratch (static globals; no cudaMalloc allowed)
// ----------------------------------------------------------------------------
__device__ float          g_X [(size_t)L_SEQ * PP_DIM];   // Bu (read-only after gemm1)
__device__ __nv_bfloat16  g_Xh[(size_t)L_SEQ * PP_DIM];   // xs rounded to bf16 (gemm2 A)
__device__ __nv_bfloat16  g_U [(size_t)L_SEQ * H_DIM];    // u rounded to bf16 (gemm1 A)
__device__ __nv_bfloat16  g_Bbh[PP_DIM * H_DIM];          // B_bar bf16 [re|im] x H
__device__ __nv_bfloat16  g_C2h[H_DIM * PP_DIM];          // [2*Cr | -2*Ci] bf16
__device__ float2 g_lam[P_DIM];
__device__ float2 g_gamma[P_DIM];
__device__ float2 g_lamS[P_DIM];
__device__ float2 g_b[NCHUNK][P_DIM];
__device__ float2 g_pref[NCHUNK][P_DIM];

// ----------------------------------------------------------------------------
// prep: Lambda_bar, gamma, lam^S (fp32 rounding points match jax; transcendentals
// in double)
// ----------------------------------------------------------------------------
__global__ void prep_kernel(const float* __restrict__ Lre,
                            const float* __restrict__ Lim,
                            const float* __restrict__ log_step)
{
    int p = threadIdx.x;
    float st = expf(log_step[p]);
    float ar = Lre[p] * st;
    float ai = Lim[p] * st;

    double er = exp((double)ar);
    double lr = er * cos((double)ai);
    double li = er * sin((double)ai);
    g_lam[p] = make_float2((float)lr, (float)li);

    double Lr = (double)Lre[p], Li = (double)Lim[p];
    double den = Lr * Lr + Li * Li;
    double nr = lr - 1.0, ni = li;
    g_gamma[p] = make_float2((float)((nr * Lr + ni * Li) / den),
                             (float)((ni * Lr - nr * Li) / den));

    double erS = exp((double)ar * S_CHUNK);
    double aiS = (double)ai * S_CHUNK;
    g_lamS[p] = make_float2((float)(erS * cos(aiS)), (float)(erS * sin(aiS)));
}

// Merged B_bar + C2 rounding.
__global__ void make_bc_kernel(const float* __restrict__ B,
                               const float* __restrict__ C)
{
    if (blockIdx.x < P_DIM) {
        int p = blockIdx.x;
        int h = threadIdx.x;          // 0..1023
        float2 g = g_gamma[p];
        float br = B[((size_t)p * H_DIM + h) * 2 + 0];
        float bi = B[((size_t)p * H_DIM + h) * 2 + 1];
        g_Bbh[(size_t)p * H_DIM + h]           = __float2bfloat16_rn(g.x * br - g.y * bi);
        g_Bbh[(size_t)(p + P_DIM) * H_DIM + h] = __float2bfloat16_rn(g.x * bi + g.y * br);
    } else {
        int h = blockIdx.x - P_DIM;
        int p = threadIdx.x;
        if (p < P_DIM) {
            g_C2h[(size_t)h * PP_DIM + p]         = __float2bfloat16_rn( 2.0f * C[((size_t)h * P_DIM + p) * 2 + 0]);
            g_C2h[(size_t)h * PP_DIM + P_DIM + p] = __float2bfloat16_rn(-2.0f * C[((size_t)h * P_DIM + p) * 2 + 1]);
        }
    }
}

// u (fp32) -> g_U (bf16, round-to-nearest).  8 elems / thread.
__global__ void round_u_kernel(const float* __restrict__ u)
{
    size_t i = ((size_t)blockIdx.x * blockDim.x + threadIdx.x) * 8;
    float4 a = *(const float4*)(u + i);
    float4 b = *(const float4*)(u + i + 4);
    __nv_bfloat162 h0 = __floats2bfloat162_rn(a.x, a.y);
    __nv_bfloat162 h1 = __floats2bfloat162_rn(a.z, a.w);
    __nv_bfloat162 h2 = __floats2bfloat162_rn(b.x, b.y);
    __nv_bfloat162 h3 = __floats2bfloat162_rn(b.z, b.w);
    uint4 out;
    out.x = *(uint32_t*)&h0;  out.y = *(uint32_t*)&h1;
    out.z = *(uint32_t*)&h2;  out.w = *(uint32_t*)&h3;
    *(uint4*)(g_U + i) = out;
}

// ----------------------------------------------------------------------------
// BF16 tensor-core GEMM:  C[M,N] = A[M,K] @ B[N,K]^T   (row-major, bf16 in, fp32 out)
// 128x128 tile, BK=32, 3-stage cp.async ring in 48KB static smem via XOR
// swizzle (64B rows, chunk ^= (row>>1)&3), ONE __syncthreads per K-tile,
// next-next tile loads issued before the MMA block.
// ----------------------------------------------------------------------------
#define BM 128
#define BN 128
#define BK 32
#define STAGE_ELEMS (BM * BK)            // 4096 bf16 = 8KB per matrix per stage

__device__ __forceinline__ uint32_t s2u(const void* p) {
    return (uint32_t)__cvta_generic_to_shared(p);
}
__device__ __forceinline__ void cp16(uint32_t dst, const void* src) {
    asm volatile("cp.async.cg.shared.global [%0], [%1], 16;\n" :: "r"(dst), "l"(src));
}
__device__ __forceinline__ void cp_commit() { asm volatile("cp.async.commit_group;\n"); }
__device__ __forceinline__ void cp_wait1()  { asm volatile("cp.async.wait_group 1;\n"); }
__device__ __forceinline__ void ldsm4(uint32_t& r0, uint32_t& r1, uint32_t& r2, uint32_t& r3,
                                      uint32_t addr) {
    asm volatile("ldmatrix.sync.aligned.m8n8.x4.shared.b16 {%0,%1,%2,%3}, [%4];\n"
                 : "=r"(r0), "=r"(r1), "=r"(r2), "=r"(r3) : "r"(addr));
}
__device__ __forceinline__ void mma_bf16(float c[4], const uint32_t a[4], const uint32_t b[2]) {
    asm volatile(
        "mma.sync.aligned.m16n8k16.row.col.f32.bf16.bf16.f32 "
        "{%0,%1,%2,%3}, {%4,%5,%6,%7}, {%8,%9}, {%0,%1,%2,%3};\n"
        : "+f"(c[0]), "+f"(c[1]), "+f"(c[2]), "+f"(c[3])
        : "r"(a[0]), "r"(a[1]), "r"(a[2]), "r"(a[3]), "r"(b[0]), "r"(b[1]));
}

// swizzled byte offset within one 128x32 bf16 stage: row 0..127, chunk 0..3
__device__ __forceinline__ uint32_t swz_off(int row, int chunk) {
    return (uint32_t)(row * 64 + ((chunk ^ ((row >> 1) & 3)) * 16));
}

template<int Kdim, int Ndim, bool EPI>
__device__ __forceinline__ void gemm_tc(const __nv_bfloat16* __restrict__ A,
                                        const __nv_bfloat16* __restrict__ B,
                                        float* __restrict__ Cm,
                                        const float* __restrict__ D,
                                        const float* __restrict__ U)
{
    // 3 stages x (A:8KB + B:8KB) = 48KB exactly
    __shared__ __align__(16) __nv_bfloat16 smem[3 * 2 * STAGE_ELEMS];

    const int tid  = threadIdx.x;
    const int lane = tid & 31;
    const int warp = tid >> 5;       // 8 warps: 2(m) x 4(n)
    const int wm   = warp >> 2;      // 0..1  -> 64 rows
    const int wn   = warp & 3;       // 0..3  -> 32 cols
    const int m0   = blockIdx.y * BM;
    const int n0   = blockIdx.x * BN;

    // loader: row = tid>>1 (0..127), chunks c0,c0+1 of 4 (16B each)
    const int lrow = tid >> 1;
    const int lc0  = (tid & 1) * 2;

    auto load_stage = [&](int s, int k0) {
        uint32_t sA = s2u(smem) + s * (2 * STAGE_ELEMS * 2);
        uint32_t sB = sA + STAGE_ELEMS * 2;
        const __nv_bfloat16* gA = A + (size_t)(m0 + lrow) * Kdim + k0 + lc0 * 8;
        const __nv_bfloat16* gB = B + (size_t)(n0 + lrow) * Kdim + k0 + lc0 * 8;
#pragma unroll
        for (int i = 0; i < 2; i++) {
            cp16(sA + swz_off(lrow, lc0 + i), gA + i * 8);
            cp16(sB + swz_off(lrow, lc0 + i), gB + i * 8);
        }
    };

    const int ldrow = lane & 15;
    const int ldsel = lane >> 4;

    float acc[4][4][4];
#pragma unroll
    for (int i = 0; i < 4; i++)
#pragma unroll
        for (int j = 0; j < 4; j++)
#pragma unroll
            for (int v = 0; v < 4; v++) acc[i][j][v] = 0.0f;

    auto ldsm_frags = [&](uint32_t sA, uint32_t sB, int ks,
                          uint32_t af[4][4], uint32_t bfr[4][2]) {
        const int chunk = ks * 2 + ldsel;
#pragma unroll
        for (int mt = 0; mt < 4; mt++) {
            int r = wm * 64 + mt * 16 + ldrow;
            ldsm4(af[mt][0], af[mt][1], af[mt][2], af[mt][3], sA + swz_off(r, chunk));
        }
#pragma unroll
        for (int pair = 0; pair < 2; pair++) {
            uint32_t q0, q1, q2, q3;
            int r = wn * 32 + pair * 16 + ldrow;
            ldsm4(q0, q1, q2, q3, sB + swz_off(r, chunk));
            bfr[pair * 2 + 0][0] = q0;  bfr[pair * 2 + 0][1] = q2;
            bfr[pair * 2 + 1][0] = q1;  bfr[pair * 2 + 1][1] = q3;
        }
    };

    const int Ktiles = Kdim / BK;       // 32 (gemm1) / 16 (gemm2)
    load_stage(0, 0);       cp_commit();
    load_stage(1, BK);      cp_commit();

    for (int kt = 0; kt < Ktiles; kt++) {
        cp_wait1();                     // stage kt%3 data ready
        __syncthreads();                // all reads of stage (kt+2)%3 done
        // overwrite the retired stage while we compute
        if (kt + 2 < Ktiles) load_stage((kt + 2) % 3, (kt + 2) * BK);
        cp_commit();

        const int s = kt % 3;
        uint32_t sA = s2u(smem) + s * (2 * STAGE_ELEMS * 2);
        uint32_t sB = sA + STAGE_ELEMS * 2;

#pragma unroll
        for (int ks = 0; ks < 2; ks++) {
            uint32_t af[4][4], bfr[4][2];
            ldsm_frags(sA, sB, ks, af, bfr);
#pragma unroll
            for (int mt = 0; mt < 4; mt++)
#pragma unroll
                for (int nt = 0; nt < 4; nt++)
                    mma_bf16(acc[mt][nt], af[mt], bfr[nt]);
        }
    }

    // Epilogue: per lane c0:(gid,2t) c1:(gid,2t+1) c2:(gid+8,2t) c3:(gid+8,2t+1)
    const int gid = lane >> 2;
    const int tig = lane & 3;
#pragma unroll
    for (int mt = 0; mt < 4; mt++) {
        int r0 = m0 + wm * 64 + mt * 16 + gid;
        int r1 = r0 + 8;
#pragma unroll
        for (int nt = 0; nt < 4; nt++) {
            int col = n0 + wn * 32 + nt * 8 + tig * 2;
            float c0 = acc[mt][nt][0], c1 = acc[mt][nt][1];
            float c2 = acc[mt][nt][2], c3 = acc[mt][nt][3];
            if (EPI) {
                float d0 = __ldg(&D[col]), d1 = __ldg(&D[col + 1]);
                float2 u0 = *(const float2*)&U[(size_t)r0 * Ndim + col];
                float2 u1 = *(const float2*)&U[(size_t)r1 * Ndim + col];
                c0 = fmaf(d0, u0.x, c0);  c1 = fmaf(d1, u0.y, c1);
                c2 = fmaf(d0, u1.x, c2);  c3 = fmaf(d1, u1.y, c3);
            }
            *(float2*)&Cm[(size_t)r0 * Ndim + col] = make_float2(c0, c1);
            *(float2*)&Cm[(size_t)r1 * Ndim + col] = make_float2(c2, c3);
        }
    }
}

__global__ void __launch_bounds__(256) gemm1_kernel()
{
    gemm_tc<H_DIM, PP_DIM, false>(g_U, g_Bbh, g_X, nullptr, nullptr);
}

__global__ void __launch_bounds__(256) gemm2_kernel(float* __restrict__ out,
                                                    const float* __restrict__ D,
                                                    const float* __restrict__ u)
{
    gemm_tc<PP_DIM, H_DIM, true>(g_Xh, g_C2h, out, D, u);
}

// ----------------------------------------------------------------------------
// Scan, 3 passes.  g_X (Bu) read-only; local states recomputed in pass 3.
// ----------------------------------------------------------------------------
__global__ void chunk_final_kernel()
{
    int p = threadIdx.x;
    int c = blockIdx.x;
    float2 lam = g_lam[p];
    float xr = 0.0f, xi = 0.0f;
    const float* base = g_X + (size_t)c * S_CHUNK * PP_DIM;
#pragma unroll 8
    for (int t = 0; t < S_CHUNK; t++) {
        float br = base[t * PP_DIM + p];
        float bi = base[t * PP_DIM + P_DIM + p];
        float nr = fmaf(lam.x, xr, fmaf(-lam.y, xi, br));
        float ni = fmaf(lam.x, xi, fmaf( lam.y, xr, bi));
        xr = nr; xi = ni;
    }
    g_b[c][p] = make_float2(xr, xi);
}

__global__ void carry_scan_kernel()
{
    __shared__ float2 sa[NCHUNK];
    __shared__ float2 sb[NCHUNK];
    int p = blockIdx.x;
    int c = threadIdx.x;
    float2 lS = g_lamS[p];
    float2 a = lS;
    float2 b = g_b[c][p];
    sa[c] = a; sb[c] = b;
    __syncthreads();
#pragma unroll
    for (int s = 1; s < NCHUNK; s <<= 1) {
        float2 pa, pb;
        bool act = (c >= s);
        if (act) { pa = sa[c - s]; pb = sb[c - s]; }
        __syncthreads();
        if (act) {
            float2 na, nb;
            na.x = a.x * pa.x - a.y * pa.y;
            na.y = a.x * pa.y + a.y * pa.x;
            nb.x = fmaf(a.x, pb.x, fmaf(-a.y, pb.y, b.x));
            nb.y = fmaf(a.x, pb.y, fmaf( a.y, pb.x, b.y));
            a = na; b = nb;
            sa[c] = a; sb[c] = b;
        }
        __syncthreads();
    }
    g_pref[c][p] = (c == 0) ? make_float2(0.0f, 0.0f) : sb[c - 1];
}

__global__ void scan_write_kernel()
{
    int p = threadIdx.x;
    int c = blockIdx.x;
    float2 lam = g_lam[p];
    float2 pf = g_pref[c][p];
    float xr = pf.x, xi = pf.y;
    const float* base = g_X + (size_t)c * S_CHUNK * PP_DIM;
    __nv_bfloat16* hb = g_Xh + (size_t)c * S_CHUNK * PP_DIM;
#pragma unroll 8
    for (int t = 0; t < S_CHUNK; t++) {
        float br = base[t * PP_DIM + p];
        float bi = base[t * PP_DIM + P_DIM + p];
        float nr = fmaf(lam.x, xr, fmaf(-lam.y, xi, br));
        float ni = fmaf(lam.x, xi, fmaf( lam.y, xr, bi));
        xr = nr; xi = ni;
        hb[t * PP_DIM + p]         = __float2bfloat16_rn(xr);
        hb[t * PP_DIM + P_DIM + p] = __float2bfloat16_rn(xi);
    }
}

// ----------------------------------------------------------------------------
// Launch
// ----------------------------------------------------------------------------
extern "C" void kernel_launch(void* const* d_in, const int* in_sizes, int n_in,
                              void* d_out, int out_size)
{
    const float* u   = (const float*)d_in[0];  // (L, H)
    const float* Lre = (const float*)d_in[1];  // (P,)
    const float* Lim = (const float*)d_in[2];  // (P,)
    const float* B   = (const float*)d_in[3];  // (P, H, 2)
    const float* C   = (const float*)d_in[4];  // (H, P, 2)
    const float* D   = (const float*)d_in[5];  // (H,)
    const float* ls  = (const float*)d_in[6];  // (P,)
    float* out = (float*)d_out;                // (L, H)

    prep_kernel<<<1, P_DIM>>>(Lre, Lim, ls);
    make_bc_kernel<<<P_DIM + H_DIM, H_DIM>>>(B, C);
    round_u_kernel<<<(L_SEQ * H_DIM / 8) / 256, 256>>>(u);

    // GEMM1: Bu = u @ Bb^T   -> g_X   (M=L, N=512, K=1024)
    gemm1_kernel<<<dim3(PP_DIM / BN, L_SEQ / BM), 256>>>();

    // Scan: g_X (fp32, read-only) -> g_Xh (bf16)
    chunk_final_kernel<<<NCHUNK, P_DIM>>>();
    carry_scan_kernel<<<P_DIM, NCHUNK>>>();
    scan_write_kernel<<<NCHUNK, P_DIM>>>();

    // GEMM2: out = xs @ C2^T + D .* u   (M=L, N=1024, K=512)
    gemm2_kernel<<<dim3(H_DIM / BN, L_SEQ / BM), 256>>>(out, D, u);
}

// round 13
// speedup vs baseline: 1.1068x; 1.1068x over previous
#include <cuda_runtime.h>
#include <cuda_bf16.h>
#include <cstdint>

// Problem constants
#define L_SEQ  16384
#define H_DIM  1024
#define P_DIM  256
#define PP_DIM 512          // 2*P : [re | im] planes
#define NCHUNK 256
#define S_CHUNK 64          // L = NCHUNK * S_CHUNK

// ----------------------------------------------------------------------------
// Device scratch (static globals; no cudaMalloc allowed)
// ----------------------------------------------------------------------------
__device__ float          g_X [(size_t)L_SEQ * PP_DIM];   // Bu (read-only after gemm1)
__device__ __nv_bfloat16  g_Xh[(size_t)L_SEQ * PP_DIM];   // xs rounded to bf16 (gemm2 A)
__device__ __nv_bfloat16  g_U [(size_t)L_SEQ * H_DIM];    // u rounded to bf16 (gemm1 A)
__device__ __nv_bfloat16  g_Bbh[PP_DIM * H_DIM];          // B_bar bf16 [re|im] x H
__device__ __nv_bfloat16  g_C2h[H_DIM * PP_DIM];          // [2*Cr | -2*Ci] bf16
__device__ float2 g_lam[P_DIM];
__device__ float2 g_gamma[P_DIM];
__device__ float2 g_lamS[P_DIM];
__device__ float2 g_b[NCHUNK][P_DIM];
__device__ float2 g_pref[NCHUNK][P_DIM];

// ----------------------------------------------------------------------------
// prep: Lambda_bar, gamma, lam^S (fp32 rounding points match jax; transcendentals
// in double)
// ----------------------------------------------------------------------------
__global__ void prep_kernel(const float* __restrict__ Lre,
                            const float* __restrict__ Lim,
                            const float* __restrict__ log_step)
{
    int p = threadIdx.x;
    float st = expf(log_step[p]);
    float ar = Lre[p] * st;
    float ai = Lim[p] * st;

    double er = exp((double)ar);
    double lr = er * cos((double)ai);
    double li = er * sin((double)ai);
    g_lam[p] = make_float2((float)lr, (float)li);

    double Lr = (double)Lre[p], Li = (double)Lim[p];
    double den = Lr * Lr + Li * Li;
    double nr = lr - 1.0, ni = li;
    g_gamma[p] = make_float2((float)((nr * Lr + ni * Li) / den),
                             (float)((ni * Lr - nr * Li) / den));

    double erS = exp((double)ar * S_CHUNK);
    double aiS = (double)ai * S_CHUNK;
    g_lamS[p] = make_float2((float)(erS * cos(aiS)), (float)(erS * sin(aiS)));
}

// Fused: B_bar rounding (blocks [0,256)), C2 rounding (blocks [256,512)),
// u->bf16 rounding (blocks [512, 512+8192)).  256 threads/block.
__global__ void fused_prep_kernel(const float* __restrict__ B,
                                  const float* __restrict__ C,
                                  const float* __restrict__ u)
{
    int bid = blockIdx.x;
    int tid = threadIdx.x;
    if (bid < P_DIM) {
        int p = bid;
        float2 g = g_gamma[p];
#pragma unroll
        for (int j = 0; j < 4; j++) {
            int h = tid + j * 256;
            float br = B[((size_t)p * H_DIM + h) * 2 + 0];
            float bi = B[((size_t)p * H_DIM + h) * 2 + 1];
            g_Bbh[(size_t)p * H_DIM + h]           = __float2bfloat16_rn(g.x * br - g.y * bi);
            g_Bbh[(size_t)(p + P_DIM) * H_DIM + h] = __float2bfloat16_rn(g.x * bi + g.y * br);
        }
    } else if (bid < 2 * P_DIM) {
        int p = tid;
#pragma unroll
        for (int j = 0; j < 4; j++) {
            int h = (bid - P_DIM) * 4 + j;
            g_C2h[(size_t)h * PP_DIM + p]         = __float2bfloat16_rn( 2.0f * C[((size_t)h * P_DIM + p) * 2 + 0]);
            g_C2h[(size_t)h * PP_DIM + P_DIM + p] = __float2bfloat16_rn(-2.0f * C[((size_t)h * P_DIM + p) * 2 + 1]);
        }
    } else {
        size_t i = ((size_t)(bid - 2 * P_DIM) * 256 + tid) * 8;
        float4 a = *(const float4*)(u + i);
        float4 b = *(const float4*)(u + i + 4);
        __nv_bfloat162 h0 = __floats2bfloat162_rn(a.x, a.y);
        __nv_bfloat162 h1 = __floats2bfloat162_rn(a.z, a.w);
        __nv_bfloat162 h2 = __floats2bfloat162_rn(b.x, b.y);
        __nv_bfloat162 h3 = __floats2bfloat162_rn(b.z, b.w);
        uint4 out;
        out.x = *(uint32_t*)&h0;  out.y = *(uint32_t*)&h1;
        out.z = *(uint32_t*)&h2;  out.w = *(uint32_t*)&h3;
        *(uint4*)(g_U + i) = out;
    }
}

// ----------------------------------------------------------------------------
// BF16 tensor-core GEMM:  C[M,N] = A[M,K] @ B[N,K]^T   (row-major, bf16 in, fp32 out)
// 128x128 tile, BK=32, 3-stage cp.async ring (48KB static smem, XOR swizzle,
// 64B rows).  ONE __syncthreads per K-tile; next-next-tile loads issued AFTER
// the ks0 MMA block (off the critical path); all swizzled offsets hoisted to
// registers before the loop.
// ----------------------------------------------------------------------------
#define BM 128
#define BN 128
#define BK 32
#define STAGE_BYTES 8192                 // 128 rows x 64B per matrix
#define STAGE_PAIR  (2 * STAGE_BYTES)    // A + B

__device__ __forceinline__ uint32_t s2u(const void* p) {
    return (uint32_t)__cvta_generic_to_shared(p);
}
__device__ __forceinline__ void cp16(uint32_t dst, const void* src) {
    asm volatile("cp.async.cg.shared.global [%0], [%1], 16;\n" :: "r"(dst), "l"(src));
}
__device__ __forceinline__ void cp_commit() { asm volatile("cp.async.commit_group;\n"); }
__device__ __forceinline__ void cp_wait1()  { asm volatile("cp.async.wait_group 1;\n"); }
__device__ __forceinline__ void ldsm4(uint32_t& r0, uint32_t& r1, uint32_t& r2, uint32_t& r3,
                                      uint32_t addr) {
    asm volatile("ldmatrix.sync.aligned.m8n8.x4.shared.b16 {%0,%1,%2,%3}, [%4];\n"
                 : "=r"(r0), "=r"(r1), "=r"(r2), "=r"(r3) : "r"(addr));
}
__device__ __forceinline__ void mma_bf16(float c[4], const uint32_t a[4], const uint32_t b[2]) {
    asm volatile(
        "mma.sync.aligned.m16n8k16.row.col.f32.bf16.bf16.f32 "
        "{%0,%1,%2,%3}, {%4,%5,%6,%7}, {%8,%9}, {%0,%1,%2,%3};\n"
        : "+f"(c[0]), "+f"(c[1]), "+f"(c[2]), "+f"(c[3])
        : "r"(a[0]), "r"(a[1]), "r"(a[2]), "r"(a[3]), "r"(b[0]), "r"(b[1]));
}

// swizzled byte offset within one 128x32 bf16 stage: row 0..127, chunk 0..3
// (16B chunks; conflict-free for both ldmatrix phases and cp.async stores)
__device__ __forceinline__ uint32_t swz_off(int row, int chunk) {
    return (uint32_t)(row * 64 + ((chunk ^ ((row >> 1) & 3)) * 16));
}

template<int Kdim, int Ndim, bool EPI>
__device__ __forceinline__ void gemm_tc(const __nv_bfloat16* __restrict__ A,
                                        const __nv_bfloat16* __restrict__ B,
                                        float* __restrict__ Cm,
                                        const float* __restrict__ D,
                                        const float* __restrict__ U)
{
    // 3 stages x (A:8KB + B:8KB) = 48KB exactly
    __shared__ __align__(16) __nv_bfloat16 smem[3 * STAGE_PAIR / 2];

    const int tid  = threadIdx.x;
    const int lane = tid & 31;
    const int warp = tid >> 5;       // 8 warps: 2(m) x 4(n)
    const int wm   = warp >> 2;      // 0..1  -> 64 rows
    const int wn   = warp & 3;       // 0..3  -> 32 cols
    const int m0   = blockIdx.y * BM;
    const int n0   = blockIdx.x * BN;
    const uint32_t sbase = s2u(smem);

    // loader: row = tid>>1 (0..127), chunks lc0, lc0+1 (16B each)
    const int lrow = tid >> 1;
    const int lc0  = (tid & 1) * 2;
    const uint32_t offL0 = swz_off(lrow, lc0);
    const uint32_t offL1 = swz_off(lrow, lc0 + 1);
    const __nv_bfloat16* gA0 = A + (size_t)(m0 + lrow) * Kdim + lc0 * 8;
    const __nv_bfloat16* gB0 = B + (size_t)(n0 + lrow) * Kdim + lc0 * 8;

    auto load_stage = [&](int s, int k0) {
        uint32_t sA = sbase + s * STAGE_PAIR;
        uint32_t sB = sA + STAGE_BYTES;
        cp16(sA + offL0, gA0 + k0);
        cp16(sA + offL1, gA0 + k0 + 8);
        cp16(sB + offL0, gB0 + k0);
        cp16(sB + offL1, gB0 + k0 + 8);
    };

    // hoisted ldsm offsets (constant per thread)
    const int ldrow = lane & 15;
    const int ldsel = lane >> 4;
    uint32_t offA[2][4], offB[2][2];
#pragma unroll
    for (int ks = 0; ks < 2; ks++) {
        const int chunk = ks * 2 + ldsel;
#pragma unroll
        for (int mt = 0; mt < 4; mt++)
            offA[ks][mt] = swz_off(wm * 64 + mt * 16 + ldrow, chunk);
#pragma unroll
        for (int pair = 0; pair < 2; pair++)
            offB[ks][pair] = STAGE_BYTES + swz_off(wn * 32 + pair * 16 + ldrow, chunk);
    }

    float acc[4][4][4];
#pragma unroll
    for (int i = 0; i < 4; i++)
#pragma unroll
        for (int j = 0; j < 4; j++)
#pragma unroll
            for (int v = 0; v < 4; v++) acc[i][j][v] = 0.0f;

    const int Ktiles = Kdim / BK;       // 32 (gemm1) / 16 (gemm2)
    load_stage(0, 0);       cp_commit();
    load_stage(1, BK);      cp_commit();

    int st = 0, stL = 2;                // compute stage, load-target stage
    for (int kt = 0; kt < Ktiles; kt++) {
        cp_wait1();                     // stage st data ready
        __syncthreads();                // stage stL fully retired (read in kt-1)
        const uint32_t sb = sbase + st * STAGE_PAIR;

        // ks0 fragments + MMAs
        uint32_t af0[4][4], bf0[4][2];
#pragma unroll
        for (int mt = 0; mt < 4; mt++)
            ldsm4(af0[mt][0], af0[mt][1], af0[mt][2], af0[mt][3], sb + offA[0][mt]);
#pragma unroll
        for (int pair = 0; pair < 2; pair++) {
            uint32_t q0, q1, q2, q3;
            ldsm4(q0, q1, q2, q3, sb + offB[0][pair]);
            bf0[pair * 2 + 0][0] = q0;  bf0[pair * 2 + 0][1] = q2;
            bf0[pair * 2 + 1][0] = q1;  bf0[pair * 2 + 1][1] = q3;
        }
#pragma unroll
        for (int mt = 0; mt < 4; mt++)
#pragma unroll
            for (int nt = 0; nt < 4; nt++)
                mma_bf16(acc[mt][nt], af0[mt], bf0[nt]);

        // issue loads for tile kt+2 into the retired stage (off critical path)
        if (kt + 2 < Ktiles) load_stage(stL, (kt + 2) * BK);
        cp_commit();

        // ks1 fragments + MMAs
        uint32_t af1[4][4], bf1[4][2];
#pragma unroll
        for (int mt = 0; mt < 4; mt++)
            ldsm4(af1[mt][0], af1[mt][1], af1[mt][2], af1[mt][3], sb + offA[1][mt]);
#pragma unroll
        for (int pair = 0; pair < 2; pair++) {
            uint32_t q0, q1, q2, q3;
            ldsm4(q0, q1, q2, q3, sb + offB[1][pair]);
            bf1[pair * 2 + 0][0] = q0;  bf1[pair * 2 + 0][1] = q2;
            bf1[pair * 2 + 1][0] = q1;  bf1[pair * 2 + 1][1] = q3;
        }
#pragma unroll
        for (int mt = 0; mt < 4; mt++)
#pragma unroll
            for (int nt = 0; nt < 4; nt++)
                mma_bf16(acc[mt][nt], af1[mt], bf1[nt]);

        st  = (st  == 2) ? 0 : st  + 1;
        stL = (stL == 2) ? 0 : stL + 1;
    }

    // Epilogue: per lane c0:(gid,2t) c1:(gid,2t+1) c2:(gid+8,2t) c3:(gid+8,2t+1)
    const int gid = lane >> 2;
    const int tig = lane & 3;
#pragma unroll
    for (int mt = 0; mt < 4; mt++) {
        int r0 = m0 + wm * 64 + mt * 16 + gid;
        int r1 = r0 + 8;
#pragma unroll
        for (int nt = 0; nt < 4; nt++) {
            int col = n0 + wn * 32 + nt * 8 + tig * 2;
            float c0 = acc[mt][nt][0], c1 = acc[mt][nt][1];
            float c2 = acc[mt][nt][2], c3 = acc[mt][nt][3];
            if (EPI) {
                float d0 = __ldg(&D[col]), d1 = __ldg(&D[col + 1]);
                float2 u0 = *(const float2*)&U[(size_t)r0 * Ndim + col];
                float2 u1 = *(const float2*)&U[(size_t)r1 * Ndim + col];
                c0 = fmaf(d0, u0.x, c0);  c1 = fmaf(d1, u0.y, c1);
                c2 = fmaf(d0, u1.x, c2);  c3 = fmaf(d1, u1.y, c3);
            }
            *(float2*)&Cm[(size_t)r0 * Ndim + col] = make_float2(c0, c1);
            *(float2*)&Cm[(size_t)r1 * Ndim + col] = make_float2(c2, c3);
        }
    }
}

__global__ void __launch_bounds__(256) gemm1_kernel()
{
    gemm_tc<H_DIM, PP_DIM, false>(g_U, g_Bbh, g_X, nullptr, nullptr);
}

__global__ void __launch_bounds__(256) gemm2_kernel(float* __restrict__ out,
                                                    const float* __restrict__ D,
                                                    const float* __restrict__ u)
{
    gemm_tc<PP_DIM, H_DIM, true>(g_Xh, g_C2h, out, D, u);
}

// ----------------------------------------------------------------------------
// Scan, 3 passes.  g_X (Bu) read-only; local states recomputed in pass 3.
// ----------------------------------------------------------------------------
__global__ void chunk_final_kernel()
{
    int p = threadIdx.x;
    int c = blockIdx.x;
    float2 lam = g_lam[p];
    float xr = 0.0f, xi = 0.0f;
    const float* base = g_X + (size_t)c * S_CHUNK * PP_DIM;
#pragma unroll 8
    for (int t = 0; t < S_CHUNK; t++) {
        float br = base[t * PP_DIM + p];
        float bi = base[t * PP_DIM + P_DIM + p];
        float nr = fmaf(lam.x, xr, fmaf(-lam.y, xi, br));
        float ni = fmaf(lam.x, xi, fmaf( lam.y, xr, bi));
        xr = nr; xi = ni;
    }
    g_b[c][p] = make_float2(xr, xi);
}

__global__ void carry_scan_kernel()
{
    __shared__ float2 sa[NCHUNK];
    __shared__ float2 sb[NCHUNK];
    int p = blockIdx.x;
    int c = threadIdx.x;
    float2 lS = g_lamS[p];
    float2 a = lS;
    float2 b = g_b[c][p];
    sa[c] = a; sb[c] = b;
    __syncthreads();
#pragma unroll
    for (int s = 1; s < NCHUNK; s <<= 1) {
        float2 pa, pb;
        bool act = (c >= s);
        if (act) { pa = sa[c - s]; pb = sb[c - s]; }
        __syncthreads();
        if (act) {
            float2 na, nb;
            na.x = a.x * pa.x - a.y * pa.y;
            na.y = a.x * pa.y + a.y * pa.x;
            nb.x = fmaf(a.x, pb.x, fmaf(-a.y, pb.y, b.x));
            nb.y = fmaf(a.x, pb.y, fmaf( a.y, pb.x, b.y));
            a = na; b = nb;
            sa[c] = a; sb[c] = b;
        }
        __syncthreads();
    }
    g_pref[c][p] = (c == 0) ? make_float2(0.0f, 0.0f) : sb[c - 1];
}

__global__ void scan_write_kernel()
{
    int p = threadIdx.x;
    int c = blockIdx.x;
    float2 lam = g_lam[p];
    float2 pf = g_pref[c][p];
    float xr = pf.x, xi = pf.y;
    const float* base = g_X + (size_t)c * S_CHUNK * PP_DIM;
    __nv_bfloat16* hb = g_Xh + (size_t)c * S_CHUNK * PP_DIM;
#pragma unroll 8
    for (int t = 0; t < S_CHUNK; t++) {
        float br = base[t * PP_DIM + p];
        float bi = base[t * PP_DIM + P_DIM + p];
        float nr = fmaf(lam.x, xr, fmaf(-lam.y, xi, br));
        float ni = fmaf(lam.x, xi, fmaf( lam.y, xr, bi));
        xr = nr; xi = ni;
        hb[t * PP_DIM + p]         = __float2bfloat16_rn(xr);
        hb[t * PP_DIM + P_DIM + p] = __float2bfloat16_rn(xi);
    }
}

// ----------------------------------------------------------------------------
// Launch
// ----------------------------------------------------------------------------
extern "C" void kernel_launch(void* const* d_in, const int* in_sizes, int n_in,
                              void* d_out, int out_size)
{
    const float* u   = (const float*)d_in[0];  // (L, H)
    const float* Lre = (const float*)d_in[1];  // (P,)
    const float* Lim = (const float*)d_in[2];  // (P,)
    const float* B   = (const float*)d_in[3];  // (P, H, 2)
    const float* C   = (const float*)d_in[4];  // (H, P, 2)
    const float* D   = (const float*)d_in[5];  // (H,)
    const float* ls  = (const float*)d_in[6];  // (P,)
    float* out = (float*)d_out;                // (L, H)

    prep_kernel<<<1, P_DIM>>>(Lre, Lim, ls);
    fused_prep_kernel<<<2 * P_DIM + (L_SEQ * H_DIM / 8) / 256, 256>>>(B, C, u);

    // GEMM1: Bu = u @ Bb^T   -> g_X   (M=L, N=512, K=1024)
    gemm1_kernel<<<dim3(PP_DIM / BN, L_SEQ / BM), 256>>>();

    // Scan: g_X (fp32, read-only) -> g_Xh (bf16)
    chunk_final_kernel<<<NCHUNK, P_DIM>>>();
    carry_scan_kernel<<<P_DIM, NCHUNK>>>();
    scan_write_kernel<<<NCHUNK, P_DIM>>>();

    // GEMM2: out = xs @ C2^T + D .* u   (M=L, N=1024, K=512)
    gemm2_kernel<<<dim3(H_DIM / BN, L_SEQ / BM), 256>>>(out, D, u);
}

// round 14
// speedup vs baseline: 1.1370x; 1.0273x over previous
#include <cuda_runtime.h>
#include <cuda_bf16.h>
#include <cstdint>

// Problem constants
#define L_SEQ  16384
#define H_DIM  1024
#define P_DIM  256
#define PP_DIM 512          // 2*P : [re | im] planes
#define NCHUNK 512
#define S_CHUNK 32          // L = NCHUNK * S_CHUNK

// ----------------------------------------------------------------------------
// Device scratch (static globals; no cudaMalloc allowed)
// ----------------------------------------------------------------------------
__device__ float          g_X [(size_t)L_SEQ * PP_DIM];   // Bu (read-only after gemm1)
__device__ __nv_bfloat16  g_Xh[(size_t)L_SEQ * PP_DIM];   // xs rounded to bf16 (gemm2 A)
__device__ __nv_bfloat16  g_U [(size_t)L_SEQ * H_DIM];    // u rounded to bf16 (gemm1 A)
__device__ __nv_bfloat16  g_Bbh[PP_DIM * H_DIM];          // B_bar bf16 [re|im] x H
__device__ __nv_bfloat16  g_C2h[H_DIM * PP_DIM];          // [2*Cr | -2*Ci] bf16
__device__ float2 g_lam[P_DIM];
__device__ float2 g_gamma[P_DIM];
__device__ float2 g_lamS[P_DIM];
__device__ float2 g_b[NCHUNK][P_DIM];
__device__ float2 g_pref[NCHUNK][P_DIM];

// ----------------------------------------------------------------------------
// prep: Lambda_bar, gamma, lam^S (fp32 rounding points match jax; transcendentals
// in double)
// ----------------------------------------------------------------------------
__global__ void prep_kernel(const float* __restrict__ Lre,
                            const float* __restrict__ Lim,
                            const float* __restrict__ log_step)
{
    int p = threadIdx.x;
    float st = expf(log_step[p]);
    float ar = Lre[p] * st;
    float ai = Lim[p] * st;

    double er = exp((double)ar);
    double lr = er * cos((double)ai);
    double li = er * sin((double)ai);
    g_lam[p] = make_float2((float)lr, (float)li);

    double Lr = (double)Lre[p], Li = (double)Lim[p];
    double den = Lr * Lr + Li * Li;
    double nr = lr - 1.0, ni = li;
    g_gamma[p] = make_float2((float)((nr * Lr + ni * Li) / den),
                             (float)((ni * Lr - nr * Li) / den));

    double erS = exp((double)ar * S_CHUNK);
    double aiS = (double)ai * S_CHUNK;
    g_lamS[p] = make_float2((float)(erS * cos(aiS)), (float)(erS * sin(aiS)));
}

// Fused: B_bar rounding (blocks [0,256)), C2 rounding (blocks [256,512)),
// u->bf16 rounding (blocks [512, 512+8192)).  256 threads/block.
__global__ void fused_prep_kernel(const float* __restrict__ B,
                                  const float* __restrict__ C,
                                  const float* __restrict__ u)
{
    int bid = blockIdx.x;
    int tid = threadIdx.x;
    if (bid < P_DIM) {
        int p = bid;
        float2 g = g_gamma[p];
#pragma unroll
        for (int j = 0; j < 4; j++) {
            int h = tid + j * 256;
            float br = B[((size_t)p * H_DIM + h) * 2 + 0];
            float bi = B[((size_t)p * H_DIM + h) * 2 + 1];
            g_Bbh[(size_t)p * H_DIM + h]           = __float2bfloat16_rn(g.x * br - g.y * bi);
            g_Bbh[(size_t)(p + P_DIM) * H_DIM + h] = __float2bfloat16_rn(g.x * bi + g.y * br);
        }
    } else if (bid < 2 * P_DIM) {
        int p = tid;
#pragma unroll
        for (int j = 0; j < 4; j++) {
            int h = (bid - P_DIM) * 4 + j;
            g_C2h[(size_t)h * PP_DIM + p]         = __float2bfloat16_rn( 2.0f * C[((size_t)h * P_DIM + p) * 2 + 0]);
            g_C2h[(size_t)h * PP_DIM + P_DIM + p] = __float2bfloat16_rn(-2.0f * C[((size_t)h * P_DIM + p) * 2 + 1]);
        }
    } else {
        size_t i = ((size_t)(bid - 2 * P_DIM) * 256 + tid) * 8;
        float4 a = *(const float4*)(u + i);
        float4 b = *(const float4*)(u + i + 4);
        __nv_bfloat162 h0 = __floats2bfloat162_rn(a.x, a.y);
        __nv_bfloat162 h1 = __floats2bfloat162_rn(a.z, a.w);
        __nv_bfloat162 h2 = __floats2bfloat162_rn(b.x, b.y);
        __nv_bfloat162 h3 = __floats2bfloat162_rn(b.z, b.w);
        uint4 out;
        out.x = *(uint32_t*)&h0;  out.y = *(uint32_t*)&h1;
        out.z = *(uint32_t*)&h2;  out.w = *(uint32_t*)&h3;
        *(uint4*)(g_U + i) = out;
    }
}

// ----------------------------------------------------------------------------
// BF16 tensor-core GEMM:  C[M,N] = A[M,K] @ B[N,K]^T   (row-major, bf16 in, fp32 out)
// 128x128 tile, BK=32, 3-stage cp.async ring (48KB static smem, XOR swizzle,
// 64B rows).  ONE __syncthreads per K-tile; next-next-tile loads issued AFTER
// the ks0 MMA block (off the critical path); all swizzled offsets hoisted to
// registers before the loop.   [FROZEN — identical to the 199.9us R13 kernel]
// ----------------------------------------------------------------------------
#define BM 128
#define BN 128
#define BK 32
#define STAGE_BYTES 8192                 // 128 rows x 64B per matrix
#define STAGE_PAIR  (2 * STAGE_BYTES)    // A + B

__device__ __forceinline__ uint32_t s2u(const void* p) {
    return (uint32_t)__cvta_generic_to_shared(p);
}
__device__ __forceinline__ void cp16(uint32_t dst, const void* src) {
    asm volatile("cp.async.cg.shared.global [%0], [%1], 16;\n" :: "r"(dst), "l"(src));
}
__device__ __forceinline__ void cp_commit() { asm volatile("cp.async.commit_group;\n"); }
__device__ __forceinline__ void cp_wait1()  { asm volatile("cp.async.wait_group 1;\n"); }
__device__ __forceinline__ void ldsm4(uint32_t& r0, uint32_t& r1, uint32_t& r2, uint32_t& r3,
                                      uint32_t addr) {
    asm volatile("ldmatrix.sync.aligned.m8n8.x4.shared.b16 {%0,%1,%2,%3}, [%4];\n"
                 : "=r"(r0), "=r"(r1), "=r"(r2), "=r"(r3) : "r"(addr));
}
__device__ __forceinline__ void mma_bf16(float c[4], const uint32_t a[4], const uint32_t b[2]) {
    asm volatile(
        "mma.sync.aligned.m16n8k16.row.col.f32.bf16.bf16.f32 "
        "{%0,%1,%2,%3}, {%4,%5,%6,%7}, {%8,%9}, {%0,%1,%2,%3};\n"
        : "+f"(c[0]), "+f"(c[1]), "+f"(c[2]), "+f"(c[3])
        : "r"(a[0]), "r"(a[1]), "r"(a[2]), "r"(a[3]), "r"(b[0]), "r"(b[1]));
}

// swizzled byte offset within one 128x32 bf16 stage: row 0..127, chunk 0..3
__device__ __forceinline__ uint32_t swz_off(int row, int chunk) {
    return (uint32_t)(row * 64 + ((chunk ^ ((row >> 1) & 3)) * 16));
}

template<int Kdim, int Ndim, bool EPI>
__device__ __forceinline__ void gemm_tc(const __nv_bfloat16* __restrict__ A,
                                        const __nv_bfloat16* __restrict__ B,
                                        float* __restrict__ Cm,
                                        const float* __restrict__ D,
                                        const float* __restrict__ U)
{
    // 3 stages x (A:8KB + B:8KB) = 48KB exactly
    __shared__ __align__(16) __nv_bfloat16 smem[3 * STAGE_PAIR / 2];

    const int tid  = threadIdx.x;
    const int lane = tid & 31;
    const int warp = tid >> 5;       // 8 warps: 2(m) x 4(n)
    const int wm   = warp >> 2;      // 0..1  -> 64 rows
    const int wn   = warp & 3;       // 0..3  -> 32 cols
    const int m0   = blockIdx.y * BM;
    const int n0   = blockIdx.x * BN;
    const uint32_t sbase = s2u(smem);

    // loader: row = tid>>1 (0..127), chunks lc0, lc0+1 (16B each)
    const int lrow = tid >> 1;
    const int lc0  = (tid & 1) * 2;
    const uint32_t offL0 = swz_off(lrow, lc0);
    const uint32_t offL1 = swz_off(lrow, lc0 + 1);
    const __nv_bfloat16* gA0 = A + (size_t)(m0 + lrow) * Kdim + lc0 * 8;
    const __nv_bfloat16* gB0 = B + (size_t)(n0 + lrow) * Kdim + lc0 * 8;

    auto load_stage = [&](int s, int k0) {
        uint32_t sA = sbase + s * STAGE_PAIR;
        uint32_t sB = sA + STAGE_BYTES;
        cp16(sA + offL0, gA0 + k0);
        cp16(sA + offL1, gA0 + k0 + 8);
        cp16(sB + offL0, gB0 + k0);
        cp16(sB + offL1, gB0 + k0 + 8);
    };

    // hoisted ldsm offsets (constant per thread)
    const int ldrow = lane & 15;
    const int ldsel = lane >> 4;
    uint32_t offA[2][4], offB[2][2];
#pragma unroll
    for (int ks = 0; ks < 2; ks++) {
        const int chunk = ks * 2 + ldsel;
#pragma unroll
        for (int mt = 0; mt < 4; mt++)
            offA[ks][mt] = swz_off(wm * 64 + mt * 16 + ldrow, chunk);
#pragma unroll
        for (int pair = 0; pair < 2; pair++)
            offB[ks][pair] = STAGE_BYTES + swz_off(wn * 32 + pair * 16 + ldrow, chunk);
    }

    float acc[4][4][4];
#pragma unroll
    for (int i = 0; i < 4; i++)
#pragma unroll
        for (int j = 0; j < 4; j++)
#pragma unroll
            for (int v = 0; v < 4; v++) acc[i][j][v] = 0.0f;

    const int Ktiles = Kdim / BK;       // 32 (gemm1) / 16 (gemm2)
    load_stage(0, 0);       cp_commit();
    load_stage(1, BK);      cp_commit();

    int st = 0, stL = 2;                // compute stage, load-target stage
    for (int kt = 0; kt < Ktiles; kt++) {
        cp_wait1();                     // stage st data ready
        __syncthreads();                // stage stL fully retired (read in kt-1)
        const uint32_t sb = sbase + st * STAGE_PAIR;

        // ks0 fragments + MMAs
        uint32_t af0[4][4], bf0[4][2];
#pragma unroll
        for (int mt = 0; mt < 4; mt++)
            ldsm4(af0[mt][0], af0[mt][1], af0[mt][2], af0[mt][3], sb + offA[0][mt]);
#pragma unroll
        for (int pair = 0; pair < 2; pair++) {
            uint32_t q0, q1, q2, q3;
            ldsm4(q0, q1, q2, q3, sb + offB[0][pair]);
            bf0[pair * 2 + 0][0] = q0;  bf0[pair * 2 + 0][1] = q2;
            bf0[pair * 2 + 1][0] = q1;  bf0[pair * 2 + 1][1] = q3;
        }
#pragma unroll
        for (int mt = 0; mt < 4; mt++)
#pragma unroll
            for (int nt = 0; nt < 4; nt++)
                mma_bf16(acc[mt][nt], af0[mt], bf0[nt]);

        // issue loads for tile kt+2 into the retired stage (off critical path)
        if (kt + 2 < Ktiles) load_stage(stL, (kt + 2) * BK);
        cp_commit();

        // ks1 fragments + MMAs
        uint32_t af1[4][4], bf1[4][2];
#pragma unroll
        for (int mt = 0; mt < 4; mt++)
            ldsm4(af1[mt][0], af1[mt][1], af1[mt][2], af1[mt][3], sb + offA[1][mt]);
#pragma unroll
        for (int pair = 0; pair < 2; pair++) {
            uint32_t q0, q1, q2, q3;
            ldsm4(q0, q1, q2, q3, sb + offB[1][pair]);
            bf1[pair * 2 + 0][0] = q0;  bf1[pair * 2 + 0][1] = q2;
            bf1[pair * 2 + 1][0] = q1;  bf1[pair * 2 + 1][1] = q3;
        }
#pragma unroll
        for (int mt = 0; mt < 4; mt++)
#pragma unroll
            for (int nt = 0; nt < 4; nt++)
                mma_bf16(acc[mt][nt], af1[mt], bf1[nt]);

        st  = (st  == 2) ? 0 : st  + 1;
        stL = (stL == 2) ? 0 : stL + 1;
    }

    // Epilogue: per lane c0:(gid,2t) c1:(gid,2t+1) c2:(gid+8,2t) c3:(gid+8,2t+1)
    const int gid = lane >> 2;
    const int tig = lane & 3;
#pragma unroll
    for (int mt = 0; mt < 4; mt++) {
        int r0 = m0 + wm * 64 + mt * 16 + gid;
        int r1 = r0 + 8;
#pragma unroll
        for (int nt = 0; nt < 4; nt++) {
            int col = n0 + wn * 32 + nt * 8 + tig * 2;
            float c0 = acc[mt][nt][0], c1 = acc[mt][nt][1];
            float c2 = acc[mt][nt][2], c3 = acc[mt][nt][3];
            if (EPI) {
                float d0 = __ldg(&D[col]), d1 = __ldg(&D[col + 1]);
                float2 u0 = *(const float2*)&U[(size_t)r0 * Ndim + col];
                float2 u1 = *(const float2*)&U[(size_t)r1 * Ndim + col];
                c0 = fmaf(d0, u0.x, c0);  c1 = fmaf(d1, u0.y, c1);
                c2 = fmaf(d0, u1.x, c2);  c3 = fmaf(d1, u1.y, c3);
            }
            *(float2*)&Cm[(size_t)r0 * Ndim + col] = make_float2(c0, c1);
            *(float2*)&Cm[(size_t)r1 * Ndim + col] = make_float2(c2, c3);
        }
    }
}

__global__ void __launch_bounds__(256) gemm1_kernel()
{
    gemm_tc<H_DIM, PP_DIM, false>(g_U, g_Bbh, g_X, nullptr, nullptr);
}

__global__ void __launch_bounds__(256) gemm2_kernel(float* __restrict__ out,
                                                    const float* __restrict__ D,
                                                    const float* __restrict__ u)
{
    gemm_tc<PP_DIM, H_DIM, true>(g_Xh, g_C2h, out, D, u);
}

// ----------------------------------------------------------------------------
// Scan, 3 passes.  g_X (Bu) read-only; local states recomputed in pass 3.
// NCHUNK=512 (S_CHUNK=32) -> 512 CTAs per streaming pass (~43% occ).
// ----------------------------------------------------------------------------
__global__ void chunk_final_kernel()
{
    int p = threadIdx.x;
    int c = blockIdx.x;
    float2 lam = g_lam[p];
    float xr = 0.0f, xi = 0.0f;
    const float* base = g_X + (size_t)c * S_CHUNK * PP_DIM;
#pragma unroll 8
    for (int t = 0; t < S_CHUNK; t++) {
        float br = base[t * PP_DIM + p];
        float bi = base[t * PP_DIM + P_DIM + p];
        float nr = fmaf(lam.x, xr, fmaf(-lam.y, xi, br));
        float ni = fmaf(lam.x, xi, fmaf( lam.y, xr, bi));
        xr = nr; xi = ni;
    }
    g_b[c][p] = make_float2(xr, xi);
}

__global__ void carry_scan_kernel()
{
    __shared__ float2 sa[NCHUNK];
    __shared__ float2 sb[NCHUNK];
    int p = blockIdx.x;
    int c = threadIdx.x;
    float2 lS = g_lamS[p];
    float2 a = lS;
    float2 b = g_b[c][p];
    sa[c] = a; sb[c] = b;
    __syncthreads();
#pragma unroll
    for (int s = 1; s < NCHUNK; s <<= 1) {
        float2 pa, pb;
        bool act = (c >= s);
        if (act) { pa = sa[c - s]; pb = sb[c - s]; }
        __syncthreads();
        if (act) {
            float2 na, nb;
            na.x = a.x * pa.x - a.y * pa.y;
            na.y = a.x * pa.y + a.y * pa.x;
            nb.x = fmaf(a.x, pb.x, fmaf(-a.y, pb.y, b.x));
            nb.y = fmaf(a.x, pb.y, fmaf( a.y, pb.x, b.y));
            a = na; b = nb;
            sa[c] = a; sb[c] = b;
        }
        __syncthreads();
    }
    g_pref[c][p] = (c == 0) ? make_float2(0.0f, 0.0f) : sb[c - 1];
}

__global__ void scan_write_kernel()
{
    int p = threadIdx.x;
    int c = blockIdx.x;
    float2 lam = g_lam[p];
    float2 pf = g_pref[c][p];
    float xr = pf.x, xi = pf.y;
    const float* base = g_X + (size_t)c * S_CHUNK * PP_DIM;
    __nv_bfloat16* hb = g_Xh + (size_t)c * S_CHUNK * PP_DIM;
#pragma unroll 8
    for (int t = 0; t < S_CHUNK; t++) {
        float br = base[t * PP_DIM + p];
        float bi = base[t * PP_DIM + P_DIM + p];
        float nr = fmaf(lam.x, xr, fmaf(-lam.y, xi, br));
        float ni = fmaf(lam.x, xi, fmaf( lam.y, xr, bi));
        xr = nr; xi = ni;
        hb[t * PP_DIM + p]         = __float2bfloat16_rn(xr);
        hb[t * PP_DIM + P_DIM + p] = __float2bfloat16_rn(xi);
    }
}

// ----------------------------------------------------------------------------
// Launch
// ----------------------------------------------------------------------------
extern "C" void kernel_launch(void* const* d_in, const int* in_sizes, int n_in,
                              void* d_out, int out_size)
{
    const float* u   = (const float*)d_in[0];  // (L, H)
    const float* Lre = (const float*)d_in[1];  // (P,)
    const float* Lim = (const float*)d_in[2];  // (P,)
    const float* B   = (const float*)d_in[3];  // (P, H, 2)
    const float* C   = (const float*)d_in[4];  // (H, P, 2)
    const float* D   = (const float*)d_in[5];  // (H,)
    const float* ls  = (const float*)d_in[6];  // (P,)
    float* out = (float*)d_out;                // (L, H)

    prep_kernel<<<1, P_DIM>>>(Lre, Lim, ls);
    fused_prep_kernel<<<2 * P_DIM + (L_SEQ * H_DIM / 8) / 256, 256>>>(B, C, u);

    // GEMM1: Bu = u @ Bb^T   -> g_X   (M=L, N=512, K=1024)
    gemm1_kernel<<<dim3(PP_DIM / BN, L_SEQ / BM), 256>>>();

    // Scan: g_X (fp32, read-only) -> g_Xh (bf16)
    chunk_final_kernel<<<NCHUNK, P_DIM>>>();
    carry_scan_kernel<<<P_DIM, NCHUNK>>>();
    scan_write_kernel<<<NCHUNK, P_DIM>>>();

    // GEMM2: out = xs @ C2^T + D .* u   (M=L, N=1024, K=512)
    gemm2_kernel<<<dim3(H_DIM / BN, L_SEQ / BM), 256>>>(out, D, u);
}

// round 17
// speedup vs baseline: 1.2246x; 1.0771x over previous
#include <cuda_runtime.h>
#include <cuda_bf16.h>
#include <cstdint>

// Problem constants
#define L_SEQ  16384
#define H_DIM  1024
#define P_DIM  256
#define PP_DIM 512          // 2*P : [re | im] planes
#define NCHUNK 512
#define S_CHUNK 32          // L = NCHUNK * S_CHUNK

// ----------------------------------------------------------------------------
// Device scratch (static globals; no cudaMalloc allowed)
// ----------------------------------------------------------------------------
__device__ float          g_X [(size_t)L_SEQ * PP_DIM];   // Bu (read-only after gemm1)
__device__ __nv_bfloat16  g_Xh[(size_t)L_SEQ * PP_DIM];   // xs rounded to bf16 (gemm2 A)
__device__ __nv_bfloat16  g_U [(size_t)L_SEQ * H_DIM];    // u rounded to bf16 (gemm1 A)
__device__ __nv_bfloat16  g_Bbh[PP_DIM * H_DIM];          // B_bar bf16 [re|im] x H
__device__ __nv_bfloat16  g_C2h[H_DIM * PP_DIM];          // [2*Cr | -2*Ci] bf16
__device__ float2 g_lam[P_DIM];
__device__ float2 g_gamma[P_DIM];
__device__ float2 g_lamS[P_DIM];
__device__ float2 g_b[NCHUNK][P_DIM];
__device__ float2 g_pref[NCHUNK][P_DIM];

// ----------------------------------------------------------------------------
// prep: Lambda_bar, gamma, lam^S (fp32 rounding points match jax; transcendentals
// in double)
// ----------------------------------------------------------------------------
__global__ void prep_kernel(const float* __restrict__ Lre,
                            const float* __restrict__ Lim,
                            const float* __restrict__ log_step)
{
    int p = threadIdx.x;
    float st = expf(log_step[p]);
    float ar = Lre[p] * st;
    float ai = Lim[p] * st;

    double er = exp((double)ar);
    double lr = er * cos((double)ai);
    double li = er * sin((double)ai);
    g_lam[p] = make_float2((float)lr, (float)li);

    double Lr = (double)Lre[p], Li = (double)Lim[p];
    double den = Lr * Lr + Li * Li;
    double nr = lr - 1.0, ni = li;
    g_gamma[p] = make_float2((float)((nr * Lr + ni * Li) / den),
                             (float)((ni * Lr - nr * Li) / den));

    double erS = exp((double)ar * S_CHUNK);
    double aiS = (double)ai * S_CHUNK;
    g_lamS[p] = make_float2((float)(erS * cos(aiS)), (float)(erS * sin(aiS)));
}

// Fused: B_bar rounding (blocks [0,256)), C2 rounding (blocks [256,512)),
// u->bf16 rounding (blocks [512, 512+8192)).  256 threads/block.
__global__ void fused_prep_kernel(const float* __restrict__ B,
                                  const float* __restrict__ C,
                                  const float* __restrict__ u)
{
    int bid = blockIdx.x;
    int tid = threadIdx.x;
    if (bid < P_DIM) {
        int p = bid;
        float2 g = g_gamma[p];
#pragma unroll
        for (int j = 0; j < 4; j++) {
            int h = tid + j * 256;
            float br = B[((size_t)p * H_DIM + h) * 2 + 0];
            float bi = B[((size_t)p * H_DIM + h) * 2 + 1];
            g_Bbh[(size_t)p * H_DIM + h]           = __float2bfloat16_rn(g.x * br - g.y * bi);
            g_Bbh[(size_t)(p + P_DIM) * H_DIM + h] = __float2bfloat16_rn(g.x * bi + g.y * br);
        }
    } else if (bid < 2 * P_DIM) {
        int p = tid;
#pragma unroll
        for (int j = 0; j < 4; j++) {
            int h = (bid - P_DIM) * 4 + j;
            g_C2h[(size_t)h * PP_DIM + p]         = __float2bfloat16_rn( 2.0f * C[((size_t)h * P_DIM + p) * 2 + 0]);
            g_C2h[(size_t)h * PP_DIM + P_DIM + p] = __float2bfloat16_rn(-2.0f * C[((size_t)h * P_DIM + p) * 2 + 1]);
        }
    } else {
        size_t i = ((size_t)(bid - 2 * P_DIM) * 256 + tid) * 8;
        float4 a = *(const float4*)(u + i);
        float4 b = *(const float4*)(u + i + 4);
        __nv_bfloat162 h0 = __floats2bfloat162_rn(a.x, a.y);
        __nv_bfloat162 h1 = __floats2bfloat162_rn(a.z, a.w);
        __nv_bfloat162 h2 = __floats2bfloat162_rn(b.x, b.y);
        __nv_bfloat162 h3 = __floats2bfloat162_rn(b.z, b.w);
        uint4 out;
        out.x = *(uint32_t*)&h0;  out.y = *(uint32_t*)&h1;
        out.z = *(uint32_t*)&h2;  out.w = *(uint32_t*)&h3;
        *(uint4*)(g_U + i) = out;
    }
}

// ----------------------------------------------------------------------------
// BF16 tensor-core GEMM:  C[M,N] = A[M,K] @ B[N,K]^T   (row-major, bf16 in, fp32 out)
// 64x128 tile, BK=32, 3-stage cp.async ring (36KB static smem, XOR swizzle,
// 64B rows).  8 warps 2(m)x4(n), 32x32 each -> 32 acc regs -> 3 CTAs/SM.
// ONE __syncthreads per K-tile; next-next-tile loads after the ks0 MMA block.
// ----------------------------------------------------------------------------
#define BM 64
#define BN 128
#define BK 32
#define A_STAGE_BYTES 4096               // 64 rows x 64B
#define B_STAGE_BYTES 8192               // 128 rows x 64B
#define STAGE_PAIR  (A_STAGE_BYTES + B_STAGE_BYTES)   // 12288

__device__ __forceinline__ uint32_t s2u(const void* p) {
    return (uint32_t)__cvta_generic_to_shared(p);
}
__device__ __forceinline__ void cp16(uint32_t dst, const void* src) {
    asm volatile("cp.async.cg.shared.global [%0], [%1], 16;\n" :: "r"(dst), "l"(src));
}
__device__ __forceinline__ void cp_commit() { asm volatile("cp.async.commit_group;\n"); }
__device__ __forceinline__ void cp_wait1()  { asm volatile("cp.async.wait_group 1;\n"); }
__device__ __forceinline__ void ldsm4(uint32_t& r0, uint32_t& r1, uint32_t& r2, uint32_t& r3,
                                      uint32_t addr) {
    asm volatile("ldmatrix.sync.aligned.m8n8.x4.shared.b16 {%0,%1,%2,%3}, [%4];\n"
                 : "=r"(r0), "=r"(r1), "=r"(r2), "=r"(r3) : "r"(addr));
}
__device__ __forceinline__ void mma_bf16(float c[4], const uint32_t a[4], const uint32_t b[2]) {
    asm volatile(
        "mma.sync.aligned.m16n8k16.row.col.f32.bf16.bf16.f32 "
        "{%0,%1,%2,%3}, {%4,%5,%6,%7}, {%8,%9}, {%0,%1,%2,%3};\n"
        : "+f"(c[0]), "+f"(c[1]), "+f"(c[2]), "+f"(c[3])
        : "r"(a[0]), "r"(a[1]), "r"(a[2]), "r"(a[3]), "r"(b[0]), "r"(b[1]));
}

// swizzled byte offset within a [rows x 32] bf16 stage: row, chunk 0..3 (16B)
__device__ __forceinline__ uint32_t swz_off(int row, int chunk) {
    return (uint32_t)(row * 64 + ((chunk ^ ((row >> 1) & 3)) * 16));
}

template<int Kdim, int Ndim, bool EPI>
__device__ __forceinline__ void gemm_tc(const __nv_bfloat16* __restrict__ A,
                                        const __nv_bfloat16* __restrict__ B,
                                        float* __restrict__ Cm,
                                        const float* __restrict__ D,
                                        const float* __restrict__ U)
{
    // 3 stages x (A:4KB + B:8KB) = 36KB
    __shared__ __align__(16) __nv_bfloat16 smem[3 * STAGE_PAIR / 2];

    const int tid  = threadIdx.x;
    const int lane = tid & 31;
    const int warp = tid >> 5;       // 8 warps: 2(m) x 4(n)
    const int wm   = warp >> 2;      // 0..1  -> 32 rows
    const int wn   = warp & 3;       // 0..3  -> 32 cols
    const int m0   = blockIdx.y * BM;
    const int n0   = blockIdx.x * BN;
    const uint32_t sbase = s2u(smem);

    // A loader: row = tid>>2 (0..63), one 16B chunk = tid&3
    const int arow = tid >> 2;
    const int ach  = tid & 3;
    const uint32_t offLA = swz_off(arow, ach);
    const __nv_bfloat16* gA0 = A + (size_t)(m0 + arow) * Kdim + ach * 8;
    // B loader: row = tid>>1 (0..127), chunks bc0, bc0+1
    const int brow = tid >> 1;
    const int bc0  = (tid & 1) * 2;
    const uint32_t offLB0 = swz_off(brow, bc0);
    const uint32_t offLB1 = swz_off(brow, bc0 + 1);
    const __nv_bfloat16* gB0 = B + (size_t)(n0 + brow) * Kdim + bc0 * 8;

    auto load_stage = [&](int s, int k0) {
        uint32_t sA = sbase + s * STAGE_PAIR;
        uint32_t sB = sA + A_STAGE_BYTES;
        cp16(sA + offLA, gA0 + k0);
        cp16(sB + offLB0, gB0 + k0);
        cp16(sB + offLB1, gB0 + k0 + 8);
    };

    // hoisted ldsm offsets (constant per thread)
    const int ldrow = lane & 15;
    const int ldsel = lane >> 4;
    uint32_t offA[2][2], offB[2][2];
#pragma unroll
    for (int ks = 0; ks < 2; ks++) {
        const int chunk = ks * 2 + ldsel;
#pragma unroll
        for (int mt = 0; mt < 2; mt++)
            offA[ks][mt] = swz_off(wm * 32 + mt * 16 + ldrow, chunk);
#pragma unroll
        for (int pair = 0; pair < 2; pair++)
            offB[ks][pair] = A_STAGE_BYTES + swz_off(wn * 32 + pair * 16 + ldrow, chunk);
    }

    float acc[2][4][4];
#pragma unroll
    for (int i = 0; i < 2; i++)
#pragma unroll
        for (int j = 0; j < 4; j++)
#pragma unroll
            for (int v = 0; v < 4; v++) acc[i][j][v] = 0.0f;

    const int Ktiles = Kdim / BK;       // 32 (gemm1) / 16 (gemm2)
    load_stage(0, 0);       cp_commit();
    load_stage(1, BK);      cp_commit();

    int st = 0, stL = 2;                // compute stage, load-target stage
    for (int kt = 0; kt < Ktiles; kt++) {
        cp_wait1();                     // stage st data ready
        __syncthreads();                // stage stL fully retired (read in kt-1)
        const uint32_t sb = sbase + st * STAGE_PAIR;

        // ks0 fragments + MMAs
        uint32_t af0[2][4], bf0[4][2];
#pragma unroll
        for (int mt = 0; mt < 2; mt++)
            ldsm4(af0[mt][0], af0[mt][1], af0[mt][2], af0[mt][3], sb + offA[0][mt]);
#pragma unroll
        for (int pair = 0; pair < 2; pair++) {
            uint32_t q0, q1, q2, q3;
            ldsm4(q0, q1, q2, q3, sb + offB[0][pair]);
            bf0[pair * 2 + 0][0] = q0;  bf0[pair * 2 + 0][1] = q2;
            bf0[pair * 2 + 1][0] = q1;  bf0[pair * 2 + 1][1] = q3;
        }
#pragma unroll
        for (int mt = 0; mt < 2; mt++)
#pragma unroll
            for (int nt = 0; nt < 4; nt++)
                mma_bf16(acc[mt][nt], af0[mt], bf0[nt]);

        // issue loads for tile kt+2 into the retired stage (off critical path)
        if (kt + 2 < Ktiles) load_stage(stL, (kt + 2) * BK);
        cp_commit();

        // ks1 fragments + MMAs
        uint32_t af1[2][4], bf1[4][2];
#pragma unroll
        for (int mt = 0; mt < 2; mt++)
            ldsm4(af1[mt][0], af1[mt][1], af1[mt][2], af1[mt][3], sb + offA[1][mt]);
#pragma unroll
        for (int pair = 0; pair < 2; pair++) {
            uint32_t q0, q1, q2, q3;
            ldsm4(q0, q1, q2, q3, sb + offB[1][pair]);
            bf1[pair * 2 + 0][0] = q0;  bf1[pair * 2 + 0][1] = q2;
            bf1[pair * 2 + 1][0] = q1;  bf1[pair * 2 + 1][1] = q3;
        }
#pragma unroll
        for (int mt = 0; mt < 2; mt++)
#pragma unroll
            for (int nt = 0; nt < 4; nt++)
                mma_bf16(acc[mt][nt], af1[mt], bf1[nt]);

        st  = (st  == 2) ? 0 : st  + 1;
        stL = (stL == 2) ? 0 : stL + 1;
    }

    // Epilogue: per lane c0:(gid,2t) c1:(gid,2t+1) c2:(gid+8,2t) c3:(gid+8,2t+1)
    const int gid = lane >> 2;
    const int tig = lane & 3;
#pragma unroll
    for (int mt = 0; mt < 2; mt++) {
        int r0 = m0 + wm * 32 + mt * 16 + gid;
        int r1 = r0 + 8;
#pragma unroll
        for (int nt = 0; nt < 4; nt++) {
            int col = n0 + wn * 32 + nt * 8 + tig * 2;
            float c0 = acc[mt][nt][0], c1 = acc[mt][nt][1];
            float c2 = acc[mt][nt][2], c3 = acc[mt][nt][3];
            if (EPI) {
                float d0 = __ldg(&D[col]), d1 = __ldg(&D[col + 1]);
                float2 u0 = *(const float2*)&U[(size_t)r0 * Ndim + col];
                float2 u1 = *(const float2*)&U[(size_t)r1 * Ndim + col];
                c0 = fmaf(d0, u0.x, c0);  c1 = fmaf(d1, u0.y, c1);
                c2 = fmaf(d0, u1.x, c2);  c3 = fmaf(d1, u1.y, c3);
            }
            *(float2*)&Cm[(size_t)r0 * Ndim + col] = make_float2(c0, c1);
            *(float2*)&Cm[(size_t)r1 * Ndim + col] = make_float2(c2, c3);
        }
    }
}

__global__ void __launch_bounds__(256, 3) gemm1_kernel()
{
    gemm_tc<H_DIM, PP_DIM, false>(g_U, g_Bbh, g_X, nullptr, nullptr);
}

__global__ void __launch_bounds__(256, 3) gemm2_kernel(float* __restrict__ out,
                                                       const float* __restrict__ D,
                                                       const float* __restrict__ u)
{
    gemm_tc<PP_DIM, H_DIM, true>(g_Xh, g_C2h, out, D, u);
}

// ----------------------------------------------------------------------------
// Scan, 3 passes.  g_X (Bu) read-only; local states recomputed in pass 3.
// ----------------------------------------------------------------------------
__global__ void chunk_final_kernel()
{
    int p = threadIdx.x;
    int c = blockIdx.x;
    float2 lam = g_lam[p];
    float xr = 0.0f, xi = 0.0f;
    const float* base = g_X + (size_t)c * S_CHUNK * PP_DIM;
#pragma unroll 8
    for (int t = 0; t < S_CHUNK; t++) {
        float br = base[t * PP_DIM + p];
        float bi = base[t * PP_DIM + P_DIM + p];
        float nr = fmaf(lam.x, xr, fmaf(-lam.y, xi, br));
        float ni = fmaf(lam.x, xi, fmaf( lam.y, xr, bi));
        xr = nr; xi = ni;
    }
    g_b[c][p] = make_float2(xr, xi);
}

__global__ void carry_scan_kernel()
{
    __shared__ float2 sa[NCHUNK];
    __shared__ float2 sb[NCHUNK];
    int p = blockIdx.x;
    int c = threadIdx.x;
    float2 lS = g_lamS[p];
    float2 a = lS;
    float2 b = g_b[c][p];
    sa[c] = a; sb[c] = b;
    __syncthreads();
#pragma unroll
    for (int s = 1; s < NCHUNK; s <<= 1) {
        float2 pa, pb;
        bool act = (c >= s);
        if (act) { pa = sa[c - s]; pb = sb[c - s]; }
        __syncthreads();
        if (act) {
            float2 na, nb;
            na.x = a.x * pa.x - a.y * pa.y;
            na.y = a.x * pa.y + a.y * pa.x;
            nb.x = fmaf(a.x, pb.x, fmaf(-a.y, pb.y, b.x));
            nb.y = fmaf(a.x, pb.y, fmaf( a.y, pb.x, b.y));
            a = na; b = nb;
            sa[c] = a; sb[c] = b;
        }
        __syncthreads();
    }
    g_pref[c][p] = (c == 0) ? make_float2(0.0f, 0.0f) : sb[c - 1];
}

__global__ void scan_write_kernel()
{
    int p = threadIdx.x;
    int c = blockIdx.x;
    float2 lam = g_lam[p];
    float2 pf = g_pref[c][p];
    float xr = pf.x, xi = pf.y;
    const float* base = g_X + (size_t)c * S_CHUNK * PP_DIM;
    __nv_bfloat16* hb = g_Xh + (size_t)c * S_CHUNK * PP_DIM;
#pragma unroll 8
    for (int t = 0; t < S_CHUNK; t++) {
        float br = base[t * PP_DIM + p];
        float bi = base[t * PP_DIM + P_DIM + p];
        float nr = fmaf(lam.x, xr, fmaf(-lam.y, xi, br));
        float ni = fmaf(lam.x, xi, fmaf( lam.y, xr, bi));
        xr = nr; xi = ni;
        hb[t * PP_DIM + p]         = __float2bfloat16_rn(xr);
        hb[t * PP_DIM + P_DIM + p] = __float2bfloat16_rn(xi);
    }
}

// ----------------------------------------------------------------------------
// Launch
// ----------------------------------------------------------------------------
extern "C" void kernel_launch(void* const* d_in, const int* in_sizes, int n_in,
                              void* d_out, int out_size)
{
    const float* u   = (const float*)d_in[0];  // (L, H)
    const float* Lre = (const float*)d_in[1];  // (P,)
    const float* Lim = (const float*)d_in[2];  // (P,)
    const float* B   = (const float*)d_in[3];  // (P, H, 2)
    const float* C   = (const float*)d_in[4];  // (H, P, 2)
    const float* D   = (const float*)d_in[5];  // (H,)
    const float* ls  = (const float*)d_in[6];  // (P,)
    float* out = (float*)d_out;                // (L, H)

    prep_kernel<<<1, P_DIM>>>(Lre, Lim, ls);
    fused_prep_kernel<<<2 * P_DIM + (L_SEQ * H_DIM / 8) / 256, 256>>>(B, C, u);

    // GEMM1: Bu = u @ Bb^T   -> g_X   (M=L, N=512, K=1024)
    gemm1_kernel<<<dim3(PP_DIM / BN, L_SEQ / BM), 256>>>();

    // Scan: g_X (fp32, read-only) -> g_Xh (bf16)
    chunk_final_kernel<<<NCHUNK, P_DIM>>>();
    carry_scan_kernel<<<P_DIM, NCHUNK>>>();
    scan_write_kernel<<<NCHUNK, P_DIM>>>();

    // GEMM2: out = xs @ C2^T + D .* u   (M=L, N=1024, K=512)
    gemm2_kernel<<<dim3(H_DIM / BN, L_SEQ / BM), 256>>>(out, D, u);
}